// round 4
// baseline (speedup 1.0000x reference)
#include <cuda_runtime.h>

// ---------------------------------------------------------------------------
// GAT stack: 4x GATConv (H=3, O=12) + 2 linears.
// N = 50000 nodes (in_sizes[0]/24), E = 800000 edges (+N self loops).
// Strategy: CSR (dst-indexed) built once per launch; per layer:
//   transform: h = y @ W^T, al_s, al_d per node (dense, tiny)
//   aggregate: warp-per-dst-node softmax aggregation, no atomics.
// Softmax max-subtraction dropped (shift invariant; logits are O(1)).
// ---------------------------------------------------------------------------

#define N_MAX 65536
#define E_MAX 1200000  // edges + self loops with margin

__device__ float g_bufA[N_MAX * 36];
__device__ float g_bufB[N_MAX * 36];
__device__ float g_als[N_MAX * 3];
__device__ float g_ald[N_MAX * 3];
__device__ float g_y12[N_MAX * 12];
__device__ int   g_off[N_MAX + 1];
__device__ int   g_pos[N_MAX];
__device__ int   g_csr[E_MAX];

// ---------------------------- CSR build ------------------------------------

__global__ void init_counts_kernel(int N) {
    int i = blockIdx.x * blockDim.x + threadIdx.x;
    if (i < N) g_pos[i] = 1;  // self loop
}

__global__ void hist_kernel(const int* __restrict__ dst, int E) {
    int e = blockIdx.x * blockDim.x + threadIdx.x;
    if (e < E) atomicAdd(&g_pos[dst[e]], 1);
}

// Single-block chunked exclusive scan of g_pos[0..N) -> g_off, g_off[N]=total.
__global__ void scan_kernel(int N) {
    __shared__ int warpsums[32];
    __shared__ int s_carry;
    const int tid = threadIdx.x;
    const int lane = tid & 31;
    const int wid = tid >> 5;
    if (tid == 0) s_carry = 0;
    __syncthreads();
    for (int base = 0; base < N; base += 1024) {
        int i = base + tid;
        int v = (i < N) ? g_pos[i] : 0;
        // inclusive warp scan
        int x = v;
        #pragma unroll
        for (int s = 1; s < 32; s <<= 1) {
            int t = __shfl_up_sync(0xffffffffu, x, s);
            if (lane >= s) x += t;
        }
        if (lane == 31) warpsums[wid] = x;
        __syncthreads();
        if (wid == 0) {
            int w = warpsums[lane];
            #pragma unroll
            for (int s = 1; s < 32; s <<= 1) {
                int t = __shfl_up_sync(0xffffffffu, w, s);
                if (lane >= s) w += t;
            }
            warpsums[lane] = w;  // inclusive warp-sum scan
        }
        __syncthreads();
        int warpoff = (wid == 0) ? 0 : warpsums[wid - 1];
        if (i < N) g_off[i] = s_carry + warpoff + x - v;  // exclusive
        __syncthreads();
        if (tid == 1023) s_carry += warpsums[31];
        __syncthreads();
    }
    if (tid == 0) g_off[N] = s_carry;
}

__global__ void scatter_init_kernel(int N) {
    int i = blockIdx.x * blockDim.x + threadIdx.x;
    if (i < N) {
        int o = g_off[i];
        g_csr[o] = i;       // self loop first
        g_pos[i] = o + 1;   // next free slot
    }
}

__global__ void scatter_kernel(const int* __restrict__ src,
                               const int* __restrict__ dst, int E) {
    int e = blockIdx.x * blockDim.x + threadIdx.x;
    if (e < E) {
        int slot = atomicAdd(&g_pos[dst[e]], 1);
        g_csr[slot] = src[e];
    }
}

// ---------------------------- node transform --------------------------------
// h[n,36] = y[n,:] @ W^T ; als[n,h] = <h[n,h,:], a_src[h,:]>, ald likewise.

template <int IN>
__global__ void transform_kernel(const float* __restrict__ y,
                                 const float* __restrict__ W,
                                 const float* __restrict__ asrc,
                                 const float* __restrict__ adst,
                                 float* __restrict__ h,
                                 float* __restrict__ als,
                                 float* __restrict__ ald, int N) {
    __shared__ float sW[36 * IN];
    __shared__ float sAs[36], sAd[36];
    for (int i = threadIdx.x; i < 36 * IN; i += blockDim.x) sW[i] = W[i];
    if (threadIdx.x < 36) {
        sAs[threadIdx.x] = asrc[threadIdx.x];
        sAd[threadIdx.x] = adst[threadIdx.x];
    }
    __syncthreads();
    int n = blockIdx.x * blockDim.x + threadIdx.x;
    if (n >= N) return;

    float yin[IN];
    #pragma unroll
    for (int i = 0; i < IN; i++) yin[i] = y[(size_t)n * IN + i];

    #pragma unroll
    for (int hd = 0; hd < 3; hd++) {
        float s1 = 0.f, s2 = 0.f;
        for (int j = 0; j < 12; j++) {
            int o = hd * 12 + j;
            float s = 0.f;
            #pragma unroll
            for (int i = 0; i < IN; i++) s = fmaf(yin[i], sW[o * IN + i], s);
            h[(size_t)n * 36 + o] = s;
            s1 = fmaf(s, sAs[o], s1);
            s2 = fmaf(s, sAd[o], s2);
        }
        als[n * 3 + hd] = s1;
        ald[n * 3 + hd] = s2;
    }
}

// ---------------------------- edge aggregation ------------------------------
// Warp per dst node. MODE 0: out[n,36] = relu(num/ws + bias).
// MODE 2: layer-3 epilogue, out[n,12] = mean_heads(num/ws) + bias.

template <int MODE>
__global__ void aggregate_kernel(const float* __restrict__ h,
                                 const float* __restrict__ als,
                                 const float* __restrict__ ald,
                                 const float* __restrict__ bias,
                                 float* __restrict__ out, int N) {
    __shared__ float sv[8][36];
    const int gw = (blockIdx.x * blockDim.x + threadIdx.x) >> 5;
    const int lane = threadIdx.x & 31;
    const int wslot = threadIdx.x >> 5;
    if (gw >= N) return;

    const int beg = g_off[gw], end = g_off[gw + 1];
    const float ad0 = ald[gw * 3 + 0];
    const float ad1 = ald[gw * 3 + 1];
    const float ad2 = ald[gw * 3 + 2];
    const int head0 = lane / 12;  // head owning feature `lane`

    float acc0 = 0.f, acc1 = 0.f;
    float ws0 = 0.f, ws1 = 0.f, ws2 = 0.f;

    for (int base = beg; base < end; base += 32) {
        int e = base + lane;
        int s = 0;
        float w0 = 0.f, w1 = 0.f, w2 = 0.f;
        if (e < end) {
            s = g_csr[e];
            float a0 = als[s * 3 + 0] + ad0;
            float a1 = als[s * 3 + 1] + ad1;
            float a2 = als[s * 3 + 2] + ad2;
            a0 = a0 > 0.f ? a0 : 0.2f * a0;
            a1 = a1 > 0.f ? a1 : 0.2f * a1;
            a2 = a2 > 0.f ? a2 : 0.2f * a2;
            w0 = __expf(a0);
            w1 = __expf(a1);
            w2 = __expf(a2);
        }
        int cnt = min(32, end - base);
        for (int j = 0; j < cnt; j++) {
            int   sj = __shfl_sync(0xffffffffu, s, j);
            float wa = __shfl_sync(0xffffffffu, w0, j);
            float wb = __shfl_sync(0xffffffffu, w1, j);
            float wc = __shfl_sync(0xffffffffu, w2, j);
            ws0 += wa; ws1 += wb; ws2 += wc;
            const float* hr = h + (size_t)sj * 36;
            float wl = head0 == 0 ? wa : (head0 == 1 ? wb : wc);
            acc0 = fmaf(wl, hr[lane], acc0);
            if (lane < 4) acc1 = fmaf(wc, hr[32 + lane], acc1);
        }
    }

    float wsl = head0 == 0 ? ws0 : (head0 == 1 ? ws1 : ws2);
    float v0 = acc0 / (wsl + 1e-16f);
    float v1 = acc1 / (ws2 + 1e-16f);

    if (MODE == 0) {
        float o0 = v0 + bias[lane];
        out[(size_t)gw * 36 + lane] = fmaxf(o0, 0.f);
        if (lane < 4) {
            float o1 = v1 + bias[32 + lane];
            out[(size_t)gw * 36 + 32 + lane] = fmaxf(o1, 0.f);
        }
    } else {
        sv[wslot][lane] = v0;
        if (lane < 4) sv[wslot][32 + lane] = v1;
        __syncwarp();
        if (lane < 12) {
            float m = (sv[wslot][lane] + sv[wslot][12 + lane] +
                       sv[wslot][24 + lane]) * (1.f / 3.f);
            out[(size_t)gw * 12 + lane] = m + bias[lane];
        }
    }
}

// ---------------------------- final linears ---------------------------------

__global__ void final_kernel(const float* __restrict__ y12,
                             const float* __restrict__ w1,
                             const float* __restrict__ b1,
                             const float* __restrict__ w2,
                             const float* __restrict__ b2,
                             float* __restrict__ out, int N) {
    int n = blockIdx.x * blockDim.x + threadIdx.x;
    if (n >= N) return;
    float y[12];
    #pragma unroll
    for (int i = 0; i < 12; i++) y[i] = y12[(size_t)n * 12 + i];
    float t[12];
    #pragma unroll
    for (int k = 0; k < 12; k++) {
        float s = b1[k];
        #pragma unroll
        for (int i = 0; i < 12; i++) s = fmaf(y[i], w1[k * 12 + i], s);
        t[k] = s;
    }
    #pragma unroll
    for (int k = 0; k < 6; k++) {
        float s = b2[k];
        #pragma unroll
        for (int i = 0; i < 12; i++) s = fmaf(t[i], w2[k * 12 + i], s);
        out[(size_t)n * 6 + k] = s;
    }
}

// ---------------------------- launch ----------------------------------------

extern "C" void kernel_launch(void* const* d_in, const int* in_sizes, int n_in,
                              void* d_out, int out_size) {
    const float* x   = (const float*)d_in[0];
    const int*   ei  = (const int*)d_in[1];
    const float* W[4]  = {(const float*)d_in[2], (const float*)d_in[6],
                          (const float*)d_in[10], (const float*)d_in[14]};
    const float* As[4] = {(const float*)d_in[3], (const float*)d_in[7],
                          (const float*)d_in[11], (const float*)d_in[15]};
    const float* Ad[4] = {(const float*)d_in[4], (const float*)d_in[8],
                          (const float*)d_in[12], (const float*)d_in[16]};
    const float* B[4]  = {(const float*)d_in[5], (const float*)d_in[9],
                          (const float*)d_in[13], (const float*)d_in[17]};
    const float* lin1_w = (const float*)d_in[18];
    const float* lin1_b = (const float*)d_in[19];
    const float* lin2_w = (const float*)d_in[20];
    const float* lin2_b = (const float*)d_in[21];

    const int N = in_sizes[0] / 24;
    const int E = in_sizes[1] / 2;
    const int* srcArr = ei;
    const int* dstArr = ei + E;

    float *bufA, *bufB, *als, *ald, *y12;
    cudaGetSymbolAddress((void**)&bufA, g_bufA);
    cudaGetSymbolAddress((void**)&bufB, g_bufB);
    cudaGetSymbolAddress((void**)&als, g_als);
    cudaGetSymbolAddress((void**)&ald, g_ald);
    cudaGetSymbolAddress((void**)&y12, g_y12);

    const int TB = 256;
    const int nbN = (N + TB - 1) / TB;
    const int nbE = (E + TB - 1) / TB;
    const int nbW = (N * 32 + TB - 1) / TB;  // warp-per-node grids

    // CSR build (identical every call; order-of-atomics only perturbs fp
    // summation order at the ~1e-7 level, far under tolerance)
    init_counts_kernel<<<nbN, TB>>>(N);
    hist_kernel<<<nbE, TB>>>(dstArr, E);
    scan_kernel<<<1, 1024>>>(N);
    scatter_init_kernel<<<nbN, TB>>>(N);
    scatter_kernel<<<nbE, TB>>>(srcArr, dstArr, E);

    // Layer 0 (in=24)
    transform_kernel<24><<<(N + 127) / 128, 128>>>(x, W[0], As[0], Ad[0],
                                                   bufA, als, ald, N);
    aggregate_kernel<0><<<nbW, TB>>>(bufA, als, ald, B[0], bufB, N);
    // Layer 1
    transform_kernel<36><<<(N + 127) / 128, 128>>>(bufB, W[1], As[1], Ad[1],
                                                   bufA, als, ald, N);
    aggregate_kernel<0><<<nbW, TB>>>(bufA, als, ald, B[1], bufB, N);
    // Layer 2
    transform_kernel<36><<<(N + 127) / 128, 128>>>(bufB, W[2], As[2], Ad[2],
                                                   bufA, als, ald, N);
    aggregate_kernel<0><<<nbW, TB>>>(bufA, als, ald, B[2], bufB, N);
    // Layer 3 (mean over heads)
    transform_kernel<36><<<(N + 127) / 128, 128>>>(bufB, W[3], As[3], Ad[3],
                                                   bufA, als, ald, N);
    aggregate_kernel<2><<<nbW, TB>>>(bufA, als, ald, B[3], y12, N);

    final_kernel<<<nbN, TB>>>(y12, lin1_w, lin1_b, lin2_w, lin2_b,
                              (float*)d_out, N);
}